// round 14
// baseline (speedup 1.0000x reference)
#include <cuda_runtime.h>
#include <cuda_fp16.h>
#include <math.h>
#include <stdint.h>

#define NN 4096
#define DD 1024
#define WW 10
#define BAND 21
#define NSPK 8

// ---------------- device scratch (static, no allocation) ----------------
__device__ float g_raw[NN * 11];
__device__ float g_band[NN * BAND];
__device__ float g_c[NN];
__device__ float g_diag[NN];
__device__ float g_chunk[256 * DD];
__device__ float g_PreC[257 * DD];
__device__ float g_S[2 * NSPK * DD];
__device__ __half g_Yh[NN * 4 * DD];
__device__ __half g_h1h[NN * DD];
__device__ __half g_h2h[NN * DD];
__device__ __half g_Wh[10 * DD * DD];   // fp16 combined weights, [N,K]
__device__ __half g_Xh[NN * DD];        // fp16 x

// ---------------- helpers -------------------------------------------------
__device__ __forceinline__ uint32_t smem_u32(const void* p) {
    uint32_t a;
    asm("{ .reg .u64 t; cvta.to.shared.u64 t, %1; cvt.u32.u64 %0, t; }"
        : "=r"(a) : "l"(p));
    return a;
}

__device__ __forceinline__ void cp16(uint32_t dst, const void* src) {
    asm volatile("cp.async.cg.shared.global [%0], [%1], 16;"
                 :: "r"(dst), "l"(src) : "memory");
}
#define CP_COMMIT() asm volatile("cp.async.commit_group;" ::: "memory")
#define CP_WAIT2()  asm volatile("cp.async.wait_group 2;" ::: "memory")
#define CP_WAIT1()  asm volatile("cp.async.wait_group 1;" ::: "memory")
#define CP_WAIT0()  asm volatile("cp.async.wait_group 0;" ::: "memory")

__device__ __forceinline__ void mma16(float c[4], const uint32_t a[4],
                                      const uint32_t b[2]) {
    asm volatile(
        "mma.sync.aligned.m16n8k16.row.col.f32.f16.f16.f32 "
        "{%0,%1,%2,%3}, {%4,%5,%6,%7}, {%8,%9}, {%0,%1,%2,%3};"
        : "+f"(c[0]), "+f"(c[1]), "+f"(c[2]), "+f"(c[3])
        : "r"(a[0]), "r"(a[1]), "r"(a[2]), "r"(a[3]), "r"(b[0]), "r"(b[1]));
}

__device__ __forceinline__ void ldsm4(uint32_t& r0, uint32_t& r1,
                                      uint32_t& r2, uint32_t& r3, uint32_t addr) {
    asm volatile("ldmatrix.sync.aligned.m8n8.x4.shared.b16 {%0,%1,%2,%3}, [%4];"
                 : "=r"(r0), "=r"(r1), "=r"(r2), "=r"(r3) : "r"(addr));
}

// ---------------- one-time conversion: combined fp16 [N,K] weights ------
struct WCPack {
    const float* a[10];
    const float* b[10];
    float s[10];
};

__global__ __launch_bounds__(256) void conv_wc(WCPack p, __half* __restrict__ dst) {
    __shared__ float t[32][33];
    int z = blockIdx.z;
    const float* A = p.a[z];
    const float* B = p.b[z];
    float sg = p.s[z];
    __half* d = dst + (size_t)z * DD * DD;
    int bx = blockIdx.x * 32, by = blockIdx.y * 32;
    int tx = threadIdx.x & 31, ty = threadIdx.x >> 5;
    if (sg != 0.f) {
#pragma unroll
        for (int j = 0; j < 32; j += 8) {
            size_t off = (size_t)(by + ty + j) * DD + bx + tx;
            t[ty + j][tx] = A[off] + sg * B[off];
        }
    } else {
#pragma unroll
        for (int j = 0; j < 32; j += 8) {
            size_t off = (size_t)(by + ty + j) * DD + bx + tx;
            t[ty + j][tx] = A[off];
        }
    }
    __syncthreads();
#pragma unroll
    for (int j = 0; j < 32; j += 8)
        d[(size_t)(bx + ty + j) * DD + by + tx] = __float2half_rn(t[tx][ty + j]);
}

__global__ __launch_bounds__(256) void conv_x(const float* __restrict__ x,
                                              __half* __restrict__ xh) {
    size_t i = ((size_t)blockIdx.x * 256 + threadIdx.x) * 4;
    float4 v = *(const float4*)&x[i];
    *(__half2*)&xh[i] = __floats2half2_rn(v.x, v.y);
    *(__half2*)&xh[i + 2] = __floats2half2_rn(v.z, v.w);
}

// prep: zero both S buffers + init emotion output with bias
__global__ void prep(float* __restrict__ S, float* __restrict__ out,
                     const float* __restrict__ be2) {
    int idx = blockIdx.x * 256 + threadIdx.x;
    if (idx < 2 * NSPK * DD) S[idx] = 0.f;
    int e = idx - 2 * NSPK * DD;
    if (e >= 0 && e < NN * 7) out[e] = be2[e % 7];
}

// ---------------- banded logits, symmetric half, cp.async double-buffered
// raw[i][k] = dot(x_i, x_{i+k}), k = 0..10
#define AH_SMEM (2 * 26 * 256 * 4)

__global__ __launch_bounds__(512) void att_half(const float* __restrict__ x,
                                                float* __restrict__ raw) {
    extern __shared__ float hsd[];
    int i0 = blockIdx.x * 16;
    int tid = threadIdx.x, w = tid >> 5, l = tid & 31;

    auto issue = [&](int ch) {
        float* dstb = hsd + (ch & 1) * (26 * 256);
        for (int idx = tid; idx < 26 * 64; idx += 512) {
            int r = idx >> 6, c4 = (idx & 63) * 4;
            int j = i0 + r;
            uint32_t daddr = smem_u32(dstb + r * 256 + c4);
            if (j < NN) {
                cp16(daddr, &x[(size_t)j * DD + ch * 256 + c4]);
            } else {
                asm volatile("st.shared.v4.f32 [%0], {%1,%1,%1,%1};"
                             :: "r"(daddr), "f"(0.f) : "memory");
            }
        }
    };

    float acc[11];
#pragma unroll
    for (int k = 0; k < 11; k++) acc[k] = 0.f;

    issue(0);
    CP_COMMIT();
#pragma unroll
    for (int ch = 0; ch < 4; ch++) {
        if (ch < 3) {
            issue(ch + 1);
            CP_COMMIT();
            CP_WAIT1();
        } else {
            CP_WAIT0();
        }
        __syncthreads();
        const float* hb = hsd + (ch & 1) * (26 * 256);
#pragma unroll
        for (int e = 0; e < 8; e++) {
            int d = l + e * 32;
            float xv = hb[w * 256 + d];
#pragma unroll
            for (int k = 0; k < 11; k++) acc[k] += xv * hb[(w + k) * 256 + d];
        }
        __syncthreads();
    }
#pragma unroll
    for (int k = 0; k < 11; k++) {
        float v = acc[k];
#pragma unroll
        for (int o = 16; o > 0; o >>= 1) v += __shfl_down_sync(0xffffffffu, v, o);
        if (l == 0) raw[(i0 + w) * 11 + k] = v;
    }
}

// ---------------- softmax over full row (assemble from symmetric raw) ----
__global__ void att_soft(const float* __restrict__ raw, float* __restrict__ band,
                         float* __restrict__ cvec, float* __restrict__ diag) {
    int i = blockIdx.x * 128 + threadIdx.x;
    if (i >= NN) return;
    int lo = max(i - WW, 0), hi = min(i + WW, NN - 1);
    int cnt = hi - lo + 1;
    float lg[BAND];
#pragma unroll
    for (int jo = 0; jo < BAND; jo++) {
        int j = i - WW + jo;
        float v = 0.f;
        bool valid = (j >= 0 && j < NN);
        if (valid) {
            if (jo >= WW) v = raw[i * 11 + (jo - WW)];
            else v = raw[j * 11 + (WW - jo)];
        }
        lg[jo] = valid ? v : -1e30f;
    }
    float m = 0.0f;
#pragma unroll
    for (int jo = 0; jo < BAND; jo++) m = fmaxf(m, lg[jo]);
    float em = expf(-m);
    float Z = (float)(NN - cnt) * em;
    float vals[BAND];
#pragma unroll
    for (int jo = 0; jo < BAND; jo++) {
        int j = i - WW + jo;
        float v = 0.f;
        if (j >= 0 && j < NN) {
            v = expf(lg[jo] - m);
            Z += v;
        }
        vals[jo] = v;
    }
    float inv = 1.0f / Z;
#pragma unroll
    for (int jo = 0; jo < BAND; jo++) band[i * BAND + jo] = vals[jo] * inv;
    cvec[i] = em * inv;
    diag[i] = vals[WW] * inv;
}

// ---------------- scan1: 16-row chunk sums + per-speaker sums (half2) ---
__global__ __launch_bounds__(256) void scan1(const __half2* __restrict__ h2v,
                                             const int* __restrict__ spk,
                                             float2* __restrict__ chunk2,
                                             float* __restrict__ S) {
    __shared__ int sp_sh[16];
    int tid = threadIdx.x;
    int d2 = blockIdx.y * 256 + tid;  // half2 column, 0..511
    int base = blockIdx.x * 16;
    if (tid < 16) sp_sh[tid] = spk[base + tid];
    __syncthreads();
    float2 s = make_float2(0.f, 0.f);
    float2 sreg[NSPK];
#pragma unroll
    for (int k = 0; k < NSPK; k++) sreg[k] = make_float2(0.f, 0.f);
#pragma unroll
    for (int r = 0; r < 16; r++) {
        float2 v = __half22float2(h2v[(size_t)(base + r) * 512 + d2]);
        s.x += v.x; s.y += v.y;
        int sp = sp_sh[r];
#pragma unroll
        for (int k = 0; k < NSPK; k++)
            if (sp == k) { sreg[k].x += v.x; sreg[k].y += v.y; }
    }
    chunk2[(size_t)blockIdx.x * 512 + d2] = s;
#pragma unroll
    for (int k = 0; k < NSPK; k++) {
        if (sreg[k].x != 0.f) atomicAdd(&S[k * DD + 2 * d2], sreg[k].x);
        if (sreg[k].y != 0.f) atomicAdd(&S[k * DD + 2 * d2 + 1], sreg[k].y);
    }
}

// ---------------- chunkpre: exclusive prefix over 256 chunks (float2) ----
__global__ __launch_bounds__(256) void chunkpre(const float2* __restrict__ chunk2,
                                                float2* __restrict__ PreC2) {
    int tid = threadIdx.x;
    int d2 = blockIdx.y * 256 + tid;  // 0..511
    int c0 = blockIdx.x * 16;
    float2 s = make_float2(0.f, 0.f);
#pragma unroll 8
    for (int c = 0; c < c0; c++) {
        float2 v = chunk2[(size_t)c * 512 + d2];
        s.x += v.x; s.y += v.y;
    }
#pragma unroll
    for (int k = 0; k < 16; k++) {
        PreC2[(size_t)(c0 + k) * 512 + d2] = s;
        float2 v = chunk2[(size_t)(c0 + k) * 512 + d2];
        s.x += v.x; s.y += v.y;
    }
    if (blockIdx.x == 15) PreC2[(size_t)256 * 512 + d2] = s;
}

// ---------------- build Y = [ypred | ysuc | ysame | diag*h] (fp16) ------
// 2 columns/thread (half2); running piecewise sums replace the prefix array
__global__ __launch_bounds__(256) void build_y(
    const __half2* __restrict__ h2v, const float* __restrict__ PreC,
    const float* __restrict__ S, const float* __restrict__ band,
    const float* __restrict__ cvec, const float* __restrict__ diag,
    const int* __restrict__ spk, __half2* __restrict__ Y2) {
    __shared__ float a_sh[16][21];
    __shared__ float amc_sh[16][21];  // (a - c_i) if same speaker else 0
    __shared__ float c_sh[16], dg_sh[16];
    __shared__ int spi_sh[16];
    int tid = threadIdx.x;
    int i0 = blockIdx.x * 16;
    int d2 = blockIdx.y * 256 + tid;  // half2 column, 0..511

    for (int idx = tid; idx < 16 * 21; idx += 256) {
        int il = idx / 21, jo = idx - il * 21;
        int i = i0 + il, j = i - WW + jo;
        bool valid = (j >= 0 && j < NN);
        float a = valid ? band[i * BAND + jo] : 0.f;
        a_sh[il][jo] = a;
        int spj = valid ? spk[j] : -1;
        amc_sh[il][jo] = (spj == spk[i]) ? (a - cvec[i]) : 0.f;
    }
    if (tid < 16) {
        c_sh[tid] = cvec[i0 + tid];
        dg_sh[tid] = diag[i0 + tid];
        spi_sh[tid] = spk[i0 + tid];
    }
    __syncthreads();

    const int h0 = i0 - WW;
    float2 hreg[36];
#pragma unroll
    for (int r = 0; r < 36; r++) {
        int j = h0 + r;
        hreg[r] = (j >= 0 && j < NN)
                      ? __half22float2(h2v[(size_t)j * 512 + d2])
                      : make_float2(0.f, 0.f);
    }

    int c16 = i0 >> 4;
    float2 PreC0 = *(const float2*)&PreC[(size_t)c16 * DD + 2 * d2];
    float2 PreC1 = *(const float2*)&PreC[(size_t)(c16 + 1) * DD + 2 * d2];
    float2 tot = *(const float2*)&PreC[(size_t)256 * DD + 2 * d2];

    // running sums: sfx = sum hreg[10..ti+20] (reset at ti=6 to hreg[26..])
    // p_lo = sum hreg[ti..9]; p_hi = sum hreg[ti..25] (ti>=11)
    float2 sfx = make_float2(0.f, 0.f), p_lo = make_float2(0.f, 0.f),
           p_hi = make_float2(0.f, 0.f);
#pragma unroll
    for (int r = 10; r <= 20; r++) { sfx.x += hreg[r].x; sfx.y += hreg[r].y; }
#pragma unroll
    for (int r = 0; r <= 9; r++) { p_lo.x += hreg[r].x; p_lo.y += hreg[r].y; }
#pragma unroll
    for (int r = 11; r <= 25; r++) { p_hi.x += hreg[r].x; p_hi.y += hreg[r].y; }

#pragma unroll
    for (int ti = 0; ti < 16; ti++) {
        if (ti == 6) sfx = hreg[26];
        float c = c_sh[ti];
        float2 yp = make_float2(0.f, 0.f), ys = make_float2(0.f, 0.f),
               ysm = make_float2(0.f, 0.f);
#pragma unroll
        for (int jo = 0; jo < BAND; jo++) {
            float2 hv = hreg[ti + jo];
            float a = a_sh[ti][jo];
            if (jo >= WW) { yp.x += a * hv.x; yp.y += a * hv.y; }
            else          { ys.x += a * hv.x; ys.y += a * hv.y; }
            float am = amc_sh[ti][jo];
            ysm.x += am * hv.x; ysm.y += am * hv.y;
        }
        // suffix: c * (tot - Pre[min(i+W, N-1)])
        float2 PreHi;
        if (ti <= 5) { PreHi.x = PreC0.x + sfx.x; PreHi.y = PreC0.y + sfx.y; }
        else         { PreHi.x = PreC1.x + sfx.x; PreHi.y = PreC1.y + sfx.y; }
        yp.x += c * (tot.x - PreHi.x);
        yp.y += c * (tot.y - PreHi.y);
        // prefix: c * Pre[i-W-1] (when >= 0)
        if (i0 + ti >= WW + 1) {
            float2 PreP2;
            if (ti <= 10) { PreP2.x = PreC0.x - p_lo.x; PreP2.y = PreC0.y - p_lo.y; }
            else          { PreP2.x = PreC1.x - p_hi.x; PreP2.y = PreC1.y - p_hi.y; }
            ys.x += c * PreP2.x;
            ys.y += c * PreP2.y;
        }
        float2 Ss = *(const float2*)&S[(size_t)spi_sh[ti] * DD + 2 * d2];
        ysm.x += c * Ss.x; ysm.y += c * Ss.y;

        size_t b2 = (size_t)(i0 + ti) * 2048 + d2;  // half2 units (4*DD/2)
        Y2[b2] = __floats2half2_rn(yp.x, yp.y);
        Y2[b2 + 512] = __floats2half2_rn(ys.x, ys.y);
        Y2[b2 + 1024] = __floats2half2_rn(ysm.x, ysm.y);
        float dg = dg_sh[ti];
        Y2[b2 + 1536] = __floats2half2_rn(dg * hreg[ti + WW].x, dg * hreg[ti + WW].y);

        // updates for next ti
        if (ti < 15) { sfx.x += hreg[ti + 21].x; sfx.y += hreg[ti + 21].y; }
        if (ti <= 9) { p_lo.x -= hreg[ti].x; p_lo.y -= hreg[ti].y; }
        if (ti >= 11 && ti < 15) { p_hi.x -= hreg[ti].x; p_hi.y -= hreg[ti].y; }
    }
}

// ---------------- fp16 mma.sync GEMM, cp.async 3-stage, ldmatrix frags ---
struct GJob {
    const __half* Aseg[4];
    const __half* Bseg[4];
    const float* bias;
    __half* C16;
    const float* We2;
    float* outEmo;
    int nseg;
    int lda;
    int relu;
    int emo;
};

#define BKH 32
#define A_STRIDE 40
#define S_A_HALFS (128 * A_STRIDE)
#define STG_HALFS (2 * S_A_HALFS)
#define STAGES 3
#define TILE_LD 132
#define GEMM_SMEM ((128 * TILE_LD + 128 * 7) * 4)

__global__ __launch_bounds__(256, 2) void gemm_fp16(GJob job) {
    extern __shared__ __half smh[];
    const uint32_t sbase = smem_u32(smh);

    const int tid = threadIdx.x;
    const int row0 = blockIdx.y * 128;
    const int col0 = blockIdx.x * 128;
    const int KT = job.nseg * 32;
    const int lda = job.lda;

    const int wid = tid >> 5, lane = tid & 31;
    const int g = lane >> 2, t = lane & 3;
    const int wr = (wid & 1) * 64;
    const int wc = (wid >> 1) * 32;

    const uint32_t laneA =
        (uint32_t)((wr + (lane & 15)) * A_STRIDE + ((lane >> 4) << 3)) * 2;
    const uint32_t laneB =
        (uint32_t)((wc + ((lane >> 4) << 3) + (lane & 7)) * A_STRIDE +
                   (((lane >> 3) & 1) << 3)) * 2;

    float acc[4][4][4];
#pragma unroll
    for (int m = 0; m < 4; m++)
#pragma unroll
        for (int n = 0; n < 4; n++)
#pragma unroll
            for (int q = 0; q < 4; q++) acc[m][n][q] = 0.f;

    auto issue = [&](int kt) {
        int seg = kt >> 5;
        int kb = (kt & 31) * BKH;
        const __half* A = job.Aseg[seg];
        const __half* B = job.Bseg[seg];
        uint32_t st = sbase + (uint32_t)((kt % STAGES) * STG_HALFS * 2);
        uint32_t stB = st + S_A_HALFS * 2;
#pragma unroll
        for (int l = 0; l < 2; l++) {
            int q = tid + l * 256;
            int r = q >> 2, c8 = (q & 3) * 8;
            cp16(st + (uint32_t)(r * A_STRIDE + c8) * 2,
                 &A[(size_t)(row0 + r) * lda + kb + c8]);
            cp16(stB + (uint32_t)(r * A_STRIDE + c8) * 2,
                 &B[(size_t)(col0 + r) * DD + kb + c8]);
        }
    };

    issue(0);
    CP_COMMIT();
    issue(1);
    CP_COMMIT();

    for (int kt = 0; kt < KT; kt++) {
        if (kt + 2 < KT) issue(kt + 2);
        CP_COMMIT();
        CP_WAIT2();
        __syncthreads();

        uint32_t sA = sbase + (uint32_t)((kt % STAGES) * STG_HALFS * 2);
        uint32_t sB = sA + S_A_HALFS * 2;

#pragma unroll
        for (int ks = 0; ks < 2; ks++) {
            const uint32_t koff = ks * 32;
            uint32_t aF[4][4], bF[4][2];
#pragma unroll
            for (int m = 0; m < 4; m++)
                ldsm4(aF[m][0], aF[m][1], aF[m][2], aF[m][3],
                      sA + laneA + m * 1280 + koff);
#pragma unroll
            for (int j = 0; j < 2; j++) {
                uint32_t r0, r1, r2, r3;
                ldsm4(r0, r1, r2, r3, sB + laneB + j * 1280 + koff);
                bF[2 * j][0] = r0; bF[2 * j][1] = r1;
                bF[2 * j + 1][0] = r2; bF[2 * j + 1][1] = r3;
            }
#pragma unroll
            for (int m = 0; m < 4; m++)
#pragma unroll
                for (int n = 0; n < 4; n++) mma16(acc[m][n], aF[m], bF[n]);
        }
        __syncthreads();
    }

    // ---- epilogue ----
    float* tile = (float*)smh;
    float* we2s = tile + 128 * TILE_LD;
    if (job.emo) {
        CP_WAIT0();
        __syncthreads();
    }

#pragma unroll
    for (int m = 0; m < 4; m++) {
        int rl = wr + m * 16 + g;
        int r = row0 + rl;
#pragma unroll
        for (int n = 0; n < 4; n++) {
            int cl = wc + n * 8 + t * 2;
            int c = col0 + cl;
            float2 v0 = make_float2(acc[m][n][0], acc[m][n][1]);
            float2 v1 = make_float2(acc[m][n][2], acc[m][n][3]);
            if (job.bias) {
                float2 b2 = *(const float2*)&job.bias[c];
                v0.x += b2.x; v0.y += b2.y; v1.x += b2.x; v1.y += b2.y;
            }
            if (job.relu) {
                v0.x = fmaxf(v0.x, 0.f); v0.y = fmaxf(v0.y, 0.f);
                v1.x = fmaxf(v1.x, 0.f); v1.y = fmaxf(v1.y, 0.f);
            }
            if (job.C16) {
                *(__half2*)&job.C16[(size_t)r * DD + c] = __floats2half2_rn(v0.x, v0.y);
                *(__half2*)&job.C16[(size_t)(r + 8) * DD + c] = __floats2half2_rn(v1.x, v1.y);
            }
            if (job.emo) {
                tile[rl * TILE_LD + cl] = v0.x;
                tile[rl * TILE_LD + cl + 1] = v0.y;
                tile[(rl + 8) * TILE_LD + cl] = v1.x;
                tile[(rl + 8) * TILE_LD + cl + 1] = v1.y;
            }
        }
    }

    if (job.emo) {
        for (int idx = tid; idx < 128 * 7; idx += 256)
            we2s[idx] = job.We2[(size_t)(col0 + idx / 7) * 7 + (idx % 7)];
        __syncthreads();
        int row = tid >> 1, half = tid & 1;
        float e[7];
#pragma unroll
        for (int w = 0; w < 7; w++) e[w] = 0.f;
        const float* trow = tile + row * TILE_LD + half * 64;
        const float* wbase = we2s + half * 64 * 7;
#pragma unroll 4
        for (int c = 0; c < 64; c++) {
            float tv = trow[c];
            const float* wp = wbase + c * 7;
#pragma unroll
            for (int w = 0; w < 7; w++) e[w] += tv * wp[w];
        }
#pragma unroll
        for (int w = 0; w < 7; w++) e[w] += __shfl_xor_sync(0xffffffffu, e[w], 1);
        if (half == 0) {
#pragma unroll
            for (int w = 0; w < 7; w++)
                atomicAdd(&job.outEmo[(size_t)(row0 + row) * 7 + w], e[w]);
        }
    }
}

// ---------------- sentiment head (fp16 inputs) ----------------------------
__global__ void sentiment_head(const __half* __restrict__ h2,
                               const __half* __restrict__ x,
                               const float* __restrict__ Wst,
                               const float* __restrict__ bst,
                               float* __restrict__ out) {
    int i = blockIdx.x;
    int w = threadIdx.x >> 5, lane = threadIdx.x & 31;
    float acc = 0.f;
    for (int k = lane; k < DD; k += 32)
        acc += __half2float(h2[(size_t)i * DD + k]) * Wst[k * 3 + w];
    for (int k = lane; k < DD; k += 32)
        acc += __half2float(x[(size_t)i * DD + k]) * Wst[(DD + k) * 3 + w];
#pragma unroll
    for (int o = 16; o > 0; o >>= 1) acc += __shfl_down_sync(0xffffffffu, acc, o);
    if (lane == 0) out[i * 3 + w] = acc + bst[w];
}

// ---------------- launch --------------------------------------------------
extern "C" void kernel_launch(void* const* d_in, const int* in_sizes, int n_in,
                              void* d_out, int out_size) {
    const float* x = (const float*)d_in[0];
    const int* spk = (const int*)d_in[1];
    const float* Wp1 = (const float*)d_in[2];
    const float* Ws1 = (const float*)d_in[3];
    const float* Wsm1 = (const float*)d_in[4];
    const float* Wdf1 = (const float*)d_in[5];
    const float* Wp2 = (const float*)d_in[6];
    const float* Ws2 = (const float*)d_in[7];
    const float* Wsm2 = (const float*)d_in[8];
    const float* Wdf2 = (const float*)d_in[9];
    const float* Wa1 = (const float*)d_in[10];
    const float* Wa2 = (const float*)d_in[11];
    const float* We1 = (const float*)d_in[12];
    const float* be1 = (const float*)d_in[13];
    const float* We2 = (const float*)d_in[14];
    const float* be2 = (const float*)d_in[15];
    const float* Wst = (const float*)d_in[16];
    const float* bst = (const float*)d_in[17];
    float* out = (float*)d_out;

    float *raw, *band, *cvec, *diag, *chunk, *PreC, *S;
    __half *Yh, *Wh, *Xh, *h1h, *h2h;
    cudaGetSymbolAddress((void**)&raw, g_raw);
    cudaGetSymbolAddress((void**)&band, g_band);
    cudaGetSymbolAddress((void**)&cvec, g_c);
    cudaGetSymbolAddress((void**)&diag, g_diag);
    cudaGetSymbolAddress((void**)&chunk, g_chunk);
    cudaGetSymbolAddress((void**)&PreC, g_PreC);
    cudaGetSymbolAddress((void**)&S, g_S);
    cudaGetSymbolAddress((void**)&Yh, g_Yh);
    cudaGetSymbolAddress((void**)&Wh, g_Wh);
    cudaGetSymbolAddress((void**)&Xh, g_Xh);
    cudaGetSymbolAddress((void**)&h1h, g_h1h);
    cudaGetSymbolAddress((void**)&h2h, g_h2h);

    cudaFuncSetAttribute(gemm_fp16, cudaFuncAttributeMaxDynamicSharedMemorySize,
                         GEMM_SMEM);
    cudaFuncSetAttribute(att_half, cudaFuncAttributeMaxDynamicSharedMemorySize,
                         AH_SMEM);

    WCPack wp;
    const float* As[10] = {Wp1, Ws1, Wsm1, Wa1, Wp2, Ws2, Wsm2, Wa2,
                           We1, We1 + (size_t)DD * DD};
    const float* Bs[10] = {Wdf1, Wdf1, Wdf1, Wa1, Wdf2, Wdf2, Wdf2, Wa2,
                           We1, We1};
    float Sg[10] = {1.f, 1.f, -1.f, 0.f, 1.f, 1.f, -1.f, 0.f, 0.f, 0.f};
    for (int i = 0; i < 10; i++) { wp.a[i] = As[i]; wp.b[i] = Bs[i]; wp.s[i] = Sg[i]; }
    conv_wc<<<dim3(32, 32, 10), 256>>>(wp, Wh);
    conv_x<<<NN * DD / 1024, 256>>>(x, Xh);
    prep<<<(2 * NSPK * DD + NN * 7 + 255) / 256, 256>>>(S, out, be2);

    att_half<<<NN / 16, 512, AH_SMEM>>>(x, raw);
    att_soft<<<NN / 128, 128>>>(raw, band, cvec, diag);

    const __half* hin = Xh;
    __half* houts[2] = {h1h, h2h};
    dim3 ggemm(DD / 128, NN / 128);

    for (int L = 0; L < 2; L++) {
        float* SL = S + (size_t)L * NSPK * DD;
        scan1<<<dim3(256, 2), 256>>>((const __half2*)hin, spk, (float2*)chunk, SL);
        chunkpre<<<dim3(16, 2), 256>>>((const float2*)chunk, (float2*)PreC);
        build_y<<<dim3(NN / 16, 2), 256>>>((const __half2*)hin, PreC, SL, band,
                                           cvec, diag, spk, (__half2*)Yh);

        GJob jb;
        for (int s = 0; s < 4; s++) {
            jb.Aseg[s] = Yh + (size_t)s * DD;
            jb.Bseg[s] = Wh + (size_t)(L * 4 + s) * DD * DD;
        }
        jb.bias = nullptr;
        jb.C16 = houts[L];
        jb.We2 = nullptr;
        jb.outEmo = nullptr;
        jb.nseg = 4;
        jb.lda = 4 * DD;
        jb.relu = 1;
        jb.emo = 0;
        gemm_fp16<<<ggemm, 256, GEMM_SMEM>>>(jb);
        hin = houts[L];
    }

    // emotion: out[:, :7] = relu([h2|x]@We1 + be1) @ We2 + be2 (fused)
    {
        GJob jb;
        jb.Aseg[0] = h2h; jb.Aseg[1] = Xh;
        jb.Aseg[2] = nullptr; jb.Aseg[3] = nullptr;
        jb.Bseg[0] = Wh + (size_t)8 * DD * DD;
        jb.Bseg[1] = Wh + (size_t)9 * DD * DD;
        jb.Bseg[2] = nullptr; jb.Bseg[3] = nullptr;
        jb.bias = be1;
        jb.C16 = nullptr;
        jb.We2 = We2;
        jb.outEmo = out;
        jb.nseg = 2;
        jb.lda = DD;
        jb.relu = 1;
        jb.emo = 1;
        gemm_fp16<<<ggemm, 256, GEMM_SMEM>>>(jb);
    }
    sentiment_head<<<NN, 96>>>(h2h, Xh, Wst, bst, out + NN * 7);
}